// round 16
// baseline (speedup 1.0000x reference)
#include <cuda_runtime.h>
#include <math.h>
#include <stdint.h>

#define T_TOK 16384
#define EMB   1024
#define NEXP  8
#define NSLOT (T_TOK * 2)

#define BM 128
#define BN 64
#define BK 32
#define NCH (EMB / BK)

// stage: A 16KB (128 rows x 32 fp32 = 128B, XOR-swizzled 16B chunks)
//      + B  8KB (32 k-rows x 64 fp32 = 256B, k-XOR-swizzled 16B chunks)
#define STAGE_BYTES 24576
#define SM_B 16384
#define SMEM_BYTES (2 * STAGE_BYTES)   // 48 KB -> three CTAs fit per SM

// ---------------- routing / scratch state ----------------
__device__ int   g_count[NEXP];
__device__ int   g_offset[NEXP];
__device__ int   g_cursor[NEXP];
__device__ int   g_tok_e[NSLOT];
__device__ float g_tok_w[NSLOT];
__device__ int   g_tok_slot[NSLOT];
__device__ int   g_slot_token[NSLOT];
__device__ float g_h[(size_t)NSLOT * EMB];   // 134 MB: relu(x@W1+b1) per slot
__device__ float g_y[(size_t)NSLOT * EMB];   // 134 MB: (h@W2+b2) per slot

// ---------------- PTX helpers (plain-sm_100-safe) ----------------
__device__ __forceinline__ uint32_t smem_u32(const void* p) {
    uint32_t a;
    asm("{ .reg .u64 t; cvta.to.shared.u64 t, %1; cvt.u32.u64 %0, t; }" : "=r"(a) : "l"(p));
    return a;
}
__device__ __forceinline__ void ldsm4(uint32_t* r, uint32_t addr) {
    asm volatile("ldmatrix.sync.aligned.m8n8.x4.shared.b16 {%0,%1,%2,%3}, [%4];"
                 : "=r"(r[0]), "=r"(r[1]), "=r"(r[2]), "=r"(r[3]) : "r"(addr));
}
__device__ __forceinline__ uint32_t lds32(uint32_t addr) {
    uint32_t v;
    asm volatile("ld.shared.b32 %0, [%1];" : "=r"(v) : "r"(addr));
    return v;
}
__device__ __forceinline__ void mma_tf32(float* d, const uint32_t* a, uint32_t b0, uint32_t b1) {
    asm volatile("mma.sync.aligned.m16n8k8.row.col.f32.tf32.tf32.f32 "
                 "{%0,%1,%2,%3}, {%4,%5,%6,%7}, {%8,%9}, {%0,%1,%2,%3};"
                 : "+f"(d[0]), "+f"(d[1]), "+f"(d[2]), "+f"(d[3])
                 : "r"(a[0]), "r"(a[1]), "r"(a[2]), "r"(a[3]), "r"(b0), "r"(b1));
}
__device__ __forceinline__ uint32_t f2tf(float f) {   // round-to-nearest tf32
    uint32_t r;
    asm("cvt.rna.tf32.f32 %0, %1;" : "=r"(r) : "f"(f));
    return r;
}
__device__ __forceinline__ void sts128(uint32_t addr, uint32_t a, uint32_t b, uint32_t c, uint32_t d) {
    asm volatile("st.shared.v4.b32 [%0], {%1,%2,%3,%4};"
                 :: "r"(addr), "r"(a), "r"(b), "r"(c), "r"(d) : "memory");
}

// ---------------- routing kernels ----------------
__global__ void reset_kernel() {
    int i = threadIdx.x;
    if (i < NEXP) { g_count[i] = 0; g_cursor[i] = 0; }
}

__global__ __launch_bounds__(256) void gate_kernel(const float* __restrict__ x,
                                                   const float* __restrict__ gw,
                                                   const float* __restrict__ gb) {
    __shared__ float sgw[EMB * NEXP];
    for (int i = threadIdx.x; i < EMB * NEXP; i += 256) sgw[i] = gw[i];
    __syncthreads();

    int warp = threadIdx.x >> 5, lane = threadIdx.x & 31;
    int t = blockIdx.x * 8 + warp;
    if (t >= T_TOK) return;

    const float* xr = x + (size_t)t * EMB;
    float acc[NEXP];
#pragma unroll
    for (int j = 0; j < NEXP; j++) acc[j] = 0.f;
    for (int d = lane; d < EMB; d += 32) {
        float xv = xr[d];
        const float* g = &sgw[d * NEXP];
#pragma unroll
        for (int j = 0; j < NEXP; j++) acc[j] += xv * g[j];
    }
#pragma unroll
    for (int off = 16; off; off >>= 1)
#pragma unroll
        for (int j = 0; j < NEXP; j++)
            acc[j] += __shfl_xor_sync(0xffffffffu, acc[j], off);

    if (lane == 0) {
        float l[NEXP];
        float mx = -1e30f;
#pragma unroll
        for (int j = 0; j < NEXP; j++) { l[j] = acc[j] + gb[j]; mx = fmaxf(mx, l[j]); }
        float s = 0.f;
#pragma unroll
        for (int j = 0; j < NEXP; j++) { l[j] = expf(l[j] - mx); s += l[j]; }
        float inv = 1.f / s;
#pragma unroll
        for (int j = 0; j < NEXP; j++) l[j] *= inv;

        int i0 = 0;
#pragma unroll
        for (int j = 1; j < NEXP; j++) if (l[j] > l[i0]) i0 = j;
        int i1 = (i0 == 0) ? 1 : 0;
#pragma unroll
        for (int j = 0; j < NEXP; j++) if (j != i0 && l[j] > l[i1]) i1 = j;

        float w0 = 1.f / (1.f + expf(l[i1] - l[i0]));   // softmax over top-2 probs
        g_tok_e[2 * t] = i0;  g_tok_e[2 * t + 1] = i1;
        g_tok_w[2 * t] = w0;  g_tok_w[2 * t + 1] = 1.f - w0;
        atomicAdd(&g_count[i0], 1);
        atomicAdd(&g_count[i1], 1);
    }
}

__global__ void scan_kernel() {
    if (threadIdx.x == 0) {
        int s = 0;
#pragma unroll
        for (int e = 0; e < NEXP; e++) { g_offset[e] = s; s += g_count[e]; }
    }
}

__global__ void scatter_kernel() {
    int i = blockIdx.x * 256 + threadIdx.x;
    if (i >= NSLOT) return;
    int e = g_tok_e[i];
    int pos = atomicAdd(&g_cursor[e], 1);
    int slot = g_offset[e] + pos;
    g_slot_token[slot] = i >> 1;
    g_tok_slot[i] = slot;
}

// ---------------- mma.sync tf32 grouped GEMM (128x64 tile, 3 CTAs/SM target) ----------------
// PASS 1: g_h[slot] = relu(x[token] @ W1[e] + b1)
// PASS 2: g_y[slot] = g_h[slot] @ W2[e] + b2
template <int PASS>
__global__ __launch_bounds__(256, 3) void moe_mma(const float* __restrict__ X,
                                                  const float* __restrict__ W,
                                                  const float* __restrict__ Bias) {
    const int e     = blockIdx.z;
    const int cnt   = g_count[e];
    const int mbase = blockIdx.y * BM;
    if (mbase >= cnt) return;
    const int off = g_offset[e];
    const int n0  = blockIdx.x * BN;

    extern __shared__ char smem[];
    const uint32_t sb = smem_u32(smem);
    const int tid = threadIdx.x, lane = tid & 31, wid = tid >> 5;

    // ---- A loader: thread covers rows ar0+32i (i<4), one 16B chunk (acol) ----
    const int acol = tid & 7;
    const int ar0  = tid >> 3;
    const float4* ap4[4];
    uint32_t astA[4];
#pragma unroll
    for (int i = 0; i < 4; i++) {
        int r  = ar0 + 32 * i;
        int gm = mbase + r; if (gm > cnt - 1) gm = cnt - 1;   // clamp; garbage rows unstored
        const float* rowp;
        if (PASS == 1) rowp = X + (size_t)g_slot_token[off + gm] * EMB;
        else           rowp = g_h + (size_t)(off + gm) * EMB;
        ap4[i] = (const float4*)rowp + acol;
        astA[i] = r * 128 + ((acol ^ (r & 7)) << 4);
    }
    // ---- B loader: thread covers k-rows bk0, bk0+16, one float4 of n (bn4 of 16) ----
    const int bn4 = tid & 15;         // 16 float4 per 256B row
    const int bk0 = tid >> 4;         // 0..15
    const float4* bp4 = (const float4*)(W + (size_t)e * EMB * EMB + (size_t)bk0 * EMB + n0) + bn4;
    const int cnp = (bn4 & ~7) | ((bn4 ^ (bk0 & 7)) & 7);   // (bk0+16)&7 == bk0&7
    uint32_t bst[2];
#pragma unroll
    for (int i = 0; i < 2; i++)
        bst[i] = (bk0 + 16 * i) * 256 + (cnp << 4);

    // ---- fragment addressing (warp grid 4m x 2n; warp tile 32x32) ----
    const int wm = (wid >> 1) * 32, wn = (wid & 1) * 32;
    const int kc = lane >> 4;                 // ldmatrix chunk sub-index
    uint32_t rowb[2], r7[2];
#pragma unroll
    for (int mt = 0; mt < 2; mt++) {
        int row = wm + mt * 16 + ((lane >> 3) & 1) * 8 + (lane & 7);
        rowb[mt] = row * 128;
        r7[mt]   = row & 7;
    }
    const int bl = lane & 3, bg = lane >> 2;
    uint32_t bB0[4], bB1[4];
#pragma unroll
    for (int nt = 0; nt < 4; nt++) {
        int n  = wn + nt * 8 + bg;
        int cn = n >> 2, nw = n & 3;
        int c0 = (cn & ~7) | ((cn ^ bl) & 7);
        int c1 = (cn & ~7) | ((cn ^ (bl + 4)) & 7);
        bB0[nt] = bl * 256 + (c0 << 4) + nw * 4;
        bB1[nt] = (bl + 4) * 256 + (c1 << 4) + nw * 4;
    }

    float acc[2][4][4];
#pragma unroll
    for (int a = 0; a < 2; a++)
#pragma unroll
        for (int b = 0; b < 4; b++)
#pragma unroll
            for (int c = 0; c < 4; c++) acc[a][b][c] = 0.f;

    float4 av[4], bv[2];
    auto loadc = [&](int c) {
#pragma unroll
        for (int i = 0; i < 4; i++) av[i] = ap4[i][c * 8];
#pragma unroll
        for (int i = 0; i < 2; i++) bv[i] = bp4[c * 8192 + i * 4096];
    };
    auto stores = [&](int buf) {
        uint32_t base = sb + buf * STAGE_BYTES;
#pragma unroll
        for (int i = 0; i < 4; i++)
            sts128(base + astA[i], f2tf(av[i].x), f2tf(av[i].y), f2tf(av[i].z), f2tf(av[i].w));
#pragma unroll
        for (int i = 0; i < 2; i++)
            sts128(base + SM_B + bst[i], f2tf(bv[i].x), f2tf(bv[i].y), f2tf(bv[i].z), f2tf(bv[i].w));
    };
    auto compute = [&](int buf) {
        uint32_t ab = sb + buf * STAGE_BYTES;
        uint32_t bb = ab + SM_B;
#pragma unroll
        for (int ks = 0; ks < 4; ks++) {
            uint32_t Af[2][4], B0[4], B1[4];
#pragma unroll
            for (int mt = 0; mt < 2; mt++) {
                uint32_t chunk = (uint32_t)(ks * 2) + kc;
                uint32_t addr  = ab + rowb[mt] + ((chunk ^ r7[mt]) << 4);
                ldsm4(Af[mt], addr);
            }
#pragma unroll
            for (int nt = 0; nt < 4; nt++) {
                B0[nt] = lds32(bb + ks * 2048 + bB0[nt]);
                B1[nt] = lds32(bb + ks * 2048 + bB1[nt]);
            }
#pragma unroll
            for (int mt = 0; mt < 2; mt++)
#pragma unroll
                for (int nt = 0; nt < 4; nt++)
                    mma_tf32(acc[mt][nt], Af[mt], B0[nt], B1[nt]);
        }
    };

    // Schedule: compute(c); loadc(c+1); stores(c+1); sync.
    loadc(0);
    stores(0);
    __syncthreads();
#pragma unroll 1
    for (int c = 0; c < NCH; c++) {
        compute(c & 1);
        if (c + 1 < NCH) {
            loadc(c + 1);
            stores((c + 1) & 1);
        }
        __syncthreads();
    }

    // ---- epilogue ----
    float bs[4][2];
#pragma unroll
    for (int nt = 0; nt < 4; nt++) {
        int col = n0 + wn + nt * 8 + (lane & 3) * 2;
        bs[nt][0] = Bias[(size_t)e * EMB + col];
        bs[nt][1] = Bias[(size_t)e * EMB + col + 1];
    }
#pragma unroll
    for (int mt = 0; mt < 2; mt++)
#pragma unroll
        for (int h = 0; h < 2; h++) {
            int m = mbase + wm + mt * 16 + (lane >> 2) + h * 8;
            if (m >= cnt) continue;
            float* dst = (PASS == 1 ? g_h : g_y) + (size_t)(off + m) * EMB + n0 + wn;
#pragma unroll
            for (int nt = 0; nt < 4; nt++) {
                float v0 = acc[mt][nt][h * 2 + 0] + bs[nt][0];
                float v1 = acc[mt][nt][h * 2 + 1] + bs[nt][1];
                if (PASS == 1) { v0 = fmaxf(v0, 0.f); v1 = fmaxf(v1, 0.f); }
                int col = nt * 8 + (lane & 3) * 2;
                *(float2*)(dst + col) = make_float2(v0, v1);
            }
        }
}

// out[t] = w0 * y[slot(t,0)] + w1 * y[slot(t,1)]   (float4 vectorized)
__global__ __launch_bounds__(256) void combine_kernel(float* __restrict__ out) {
    int idx = blockIdx.x * 256 + threadIdx.x;     // T_TOK * EMB/4 threads
    int t   = idx >> 8;                            // EMB/4 = 256
    int d4  = idx & 255;
    int s0 = g_tok_slot[2 * t], s1 = g_tok_slot[2 * t + 1];
    float w0 = g_tok_w[2 * t], w1 = g_tok_w[2 * t + 1];
    float4 a = *((const float4*)(g_y + (size_t)s0 * EMB) + d4);
    float4 b = *((const float4*)(g_y + (size_t)s1 * EMB) + d4);
    float4 o;
    o.x = w0 * a.x + w1 * b.x;
    o.y = w0 * a.y + w1 * b.y;
    o.z = w0 * a.z + w1 * b.z;
    o.w = w0 * a.w + w1 * b.w;
    *((float4*)(out + (size_t)t * EMB) + d4) = o;
}

extern "C" void kernel_launch(void* const* d_in, const int* in_sizes, int n_in,
                              void* d_out, int out_size) {
    const float* x  = (const float*)d_in[0];
    const float* gw = (const float*)d_in[1];
    const float* gb = (const float*)d_in[2];
    const float* W1 = (const float*)d_in[3];
    const float* b1 = (const float*)d_in[4];
    const float* W2 = (const float*)d_in[5];
    const float* b2 = (const float*)d_in[6];
    float* out = (float*)d_out;

    cudaFuncSetAttribute(moe_mma<1>, cudaFuncAttributeMaxDynamicSharedMemorySize, SMEM_BYTES);
    cudaFuncSetAttribute(moe_mma<2>, cudaFuncAttributeMaxDynamicSharedMemorySize, SMEM_BYTES);

    // no memset: combine_kernel fully overwrites d_out.
    reset_kernel<<<1, 32>>>();
    gate_kernel<<<T_TOK / 8, 256>>>(x, gw, gb);
    scan_kernel<<<1, 1>>>();
    scatter_kernel<<<NSLOT / 256, 256>>>();

    dim3 grid(EMB / BN, NSLOT / BM, NEXP);
    moe_mma<1><<<grid, 256, SMEM_BYTES>>>(x, W1, b1);
    moe_mma<2><<<grid, 256, SMEM_BYTES>>>(nullptr, W2, b2);
    combine_kernel<<<T_TOK * (EMB / 4) / 256, 256>>>(out);
}

// round 17
// speedup vs baseline: 1.3595x; 1.3595x over previous
#include <cuda_runtime.h>
#include <cuda_fp16.h>
#include <math.h>
#include <stdint.h>

#define T_TOK 16384
#define EMB   1024
#define NEXP  8
#define NSLOT (T_TOK * 2)

#define BM 128
#define BN 128
#define BK 32
#define NCH (EMB / BK)

// stage: A 16KB (128 rows x 32 fp32-words = 128B, XOR-swizzled 16B chunks)
//      + B 16KB (32 k-rows x 128 n-words = 512B, k-XOR-swizzled 16B chunks)
#define STAGE_BYTES 32768
#define SM_B 16384
#define SMEM_BYTES (2 * STAGE_BYTES)   // 64 KB -> two CTAs fit per SM

// ---------------- routing / scratch state ----------------
__device__ int    g_count[NEXP];
__device__ int    g_offset[NEXP];
__device__ int    g_cursor[NEXP];
__device__ int    g_tok_e[NSLOT];
__device__ float  g_tok_w[NSLOT];
__device__ int    g_tok_slot[NSLOT];
__device__ int    g_slot_token[NSLOT];
__device__ __half g_h[(size_t)NSLOT * EMB];   // 67 MB: relu(x@W1+b1) per slot (fp16)
__device__ __half g_y[(size_t)NSLOT * EMB];   // 67 MB: (h@W2+b2) per slot (fp16)

// ---------------- PTX helpers (plain-sm_100-safe) ----------------
__device__ __forceinline__ uint32_t smem_u32(const void* p) {
    uint32_t a;
    asm("{ .reg .u64 t; cvta.to.shared.u64 t, %1; cvt.u32.u64 %0, t; }" : "=r"(a) : "l"(p));
    return a;
}
__device__ __forceinline__ void ldsm4(uint32_t* r, uint32_t addr) {
    asm volatile("ldmatrix.sync.aligned.m8n8.x4.shared.b16 {%0,%1,%2,%3}, [%4];"
                 : "=r"(r[0]), "=r"(r[1]), "=r"(r[2]), "=r"(r[3]) : "r"(addr));
}
__device__ __forceinline__ uint32_t lds32(uint32_t addr) {
    uint32_t v;
    asm volatile("ld.shared.b32 %0, [%1];" : "=r"(v) : "r"(addr));
    return v;
}
__device__ __forceinline__ void mma_tf32(float* d, const uint32_t* a, uint32_t b0, uint32_t b1) {
    asm volatile("mma.sync.aligned.m16n8k8.row.col.f32.tf32.tf32.f32 "
                 "{%0,%1,%2,%3}, {%4,%5,%6,%7}, {%8,%9}, {%0,%1,%2,%3};"
                 : "+f"(d[0]), "+f"(d[1]), "+f"(d[2]), "+f"(d[3])
                 : "r"(a[0]), "r"(a[1]), "r"(a[2]), "r"(a[3]), "r"(b0), "r"(b1));
}
__device__ __forceinline__ uint32_t f2tf(float f) {   // round-to-nearest tf32
    uint32_t r;
    asm("cvt.rna.tf32.f32 %0, %1;" : "=r"(r) : "f"(f));
    return r;
}
__device__ __forceinline__ void sts128(uint32_t addr, uint32_t a, uint32_t b, uint32_t c, uint32_t d) {
    asm volatile("st.shared.v4.b32 [%0], {%1,%2,%3,%4};"
                 :: "r"(addr), "r"(a), "r"(b), "r"(c), "r"(d) : "memory");
}

// ---------------- routing kernels ----------------
__global__ void reset_kernel() {
    int i = threadIdx.x;
    if (i < NEXP) { g_count[i] = 0; g_cursor[i] = 0; }
}

__global__ __launch_bounds__(256) void gate_kernel(const float* __restrict__ x,
                                                   const float* __restrict__ gw,
                                                   const float* __restrict__ gb) {
    __shared__ float sgw[EMB * NEXP];
    for (int i = threadIdx.x; i < EMB * NEXP; i += 256) sgw[i] = gw[i];
    __syncthreads();

    int warp = threadIdx.x >> 5, lane = threadIdx.x & 31;
    int t = blockIdx.x * 8 + warp;
    if (t >= T_TOK) return;

    const float* xr = x + (size_t)t * EMB;
    float acc[NEXP];
#pragma unroll
    for (int j = 0; j < NEXP; j++) acc[j] = 0.f;
    for (int d = lane; d < EMB; d += 32) {
        float xv = xr[d];
        const float* g = &sgw[d * NEXP];
#pragma unroll
        for (int j = 0; j < NEXP; j++) acc[j] += xv * g[j];
    }
#pragma unroll
    for (int off = 16; off; off >>= 1)
#pragma unroll
        for (int j = 0; j < NEXP; j++)
            acc[j] += __shfl_xor_sync(0xffffffffu, acc[j], off);

    if (lane == 0) {
        float l[NEXP];
        float mx = -1e30f;
#pragma unroll
        for (int j = 0; j < NEXP; j++) { l[j] = acc[j] + gb[j]; mx = fmaxf(mx, l[j]); }
        float s = 0.f;
#pragma unroll
        for (int j = 0; j < NEXP; j++) { l[j] = expf(l[j] - mx); s += l[j]; }
        float inv = 1.f / s;
#pragma unroll
        for (int j = 0; j < NEXP; j++) l[j] *= inv;

        int i0 = 0;
#pragma unroll
        for (int j = 1; j < NEXP; j++) if (l[j] > l[i0]) i0 = j;
        int i1 = (i0 == 0) ? 1 : 0;
#pragma unroll
        for (int j = 0; j < NEXP; j++) if (j != i0 && l[j] > l[i1]) i1 = j;

        float w0 = 1.f / (1.f + expf(l[i1] - l[i0]));   // softmax over top-2 probs
        g_tok_e[2 * t] = i0;  g_tok_e[2 * t + 1] = i1;
        g_tok_w[2 * t] = w0;  g_tok_w[2 * t + 1] = 1.f - w0;
        atomicAdd(&g_count[i0], 1);
        atomicAdd(&g_count[i1], 1);
    }
}

__global__ void scan_kernel() {
    if (threadIdx.x == 0) {
        int s = 0;
#pragma unroll
        for (int e = 0; e < NEXP; e++) { g_offset[e] = s; s += g_count[e]; }
    }
}

__global__ void scatter_kernel() {
    int i = blockIdx.x * 256 + threadIdx.x;
    if (i >= NSLOT) return;
    int e = g_tok_e[i];
    int pos = atomicAdd(&g_cursor[e], 1);
    int slot = g_offset[e] + pos;
    g_slot_token[slot] = i >> 1;
    g_tok_slot[i] = slot;
}

// ---------------- mma.sync tf32 grouped GEMM (R15 champion, fp16 intermediates) ----------------
// PASS 1: g_h[slot] = fp16( relu(x[token] @ W1[e] + b1) )
// PASS 2: g_y[slot] = fp16( h[slot] @ W2[e] + b2 )
template <int PASS>
__global__ __launch_bounds__(256, 2) void moe_mma(const float* __restrict__ X,
                                                  const float* __restrict__ W,
                                                  const float* __restrict__ Bias) {
    const int e     = blockIdx.z;
    const int cnt   = g_count[e];
    const int mbase = blockIdx.y * BM;
    if (mbase >= cnt) return;
    const int off = g_offset[e];
    const int n0  = blockIdx.x * BN;

    extern __shared__ char smem[];
    const uint32_t sb = smem_u32(smem);
    const int tid = threadIdx.x, lane = tid & 31, wid = tid >> 5;

    // ---- A loader: thread covers rows ar0+32i (i<4), one 16B chunk (acol) ----
    // PASS1: fp32 x rows (float4 per chunk-slot). PASS2: fp16 h rows (uint2 = 4 halfs).
    const int acol = tid & 7;
    const int ar0  = tid >> 3;
    const float4* ap4[4];    // PASS1
    const uint2*  ah2[4];    // PASS2
    uint32_t astA[4];
#pragma unroll
    for (int i = 0; i < 4; i++) {
        int r  = ar0 + 32 * i;
        int gm = mbase + r; if (gm > cnt - 1) gm = cnt - 1;   // clamp; garbage rows unstored
        if (PASS == 1) {
            const float* rowp = X + (size_t)g_slot_token[off + gm] * EMB;
            ap4[i] = (const float4*)rowp + acol;
        } else {
            const __half* rowp = g_h + (size_t)(off + gm) * EMB;
            ah2[i] = (const uint2*)rowp + acol;
        }
        astA[i] = r * 128 + ((acol ^ (r & 7)) << 4);
    }
    // ---- B loader: thread covers k-rows bk0+8i (i<4), one float4 of n (bn4) ----
    const int bn4 = tid & 31;
    const int bk0 = tid >> 5;
    const float4* bp4 = (const float4*)(W + (size_t)e * EMB * EMB + (size_t)bk0 * EMB + n0) + bn4;
    const int cnp = (bn4 & ~7) | ((bn4 ^ bk0) & 7);   // k&7 == bk0 for all i
    uint32_t bst[4];
#pragma unroll
    for (int i = 0; i < 4; i++)
        bst[i] = (bk0 + 8 * i) * 512 + (cnp << 4);

    // ---- fragment addressing (A recomputed in-loop to save registers) ----
    const int wm = (wid >> 2) * 64, wn = (wid & 3) * 32;
    const int kc = lane >> 4;
    uint32_t rowb[4], r7[4];
#pragma unroll
    for (int mt = 0; mt < 4; mt++) {
        int row = wm + mt * 16 + ((lane >> 3) & 1) * 8 + (lane & 7);
        rowb[mt] = row * 128;
        r7[mt]   = row & 7;
    }
    const int bl = lane & 3, bg = lane >> 2;
    uint32_t bB0[4], bB1[4];
#pragma unroll
    for (int nt = 0; nt < 4; nt++) {
        int n  = wn + nt * 8 + bg;
        int cn = n >> 2, nw = n & 3;
        int c0 = (cn & ~7) | ((cn ^ bl) & 7);
        int c1 = (cn & ~7) | ((cn ^ (bl + 4)) & 7);
        bB0[nt] = bl * 512 + (c0 << 4) + nw * 4;
        bB1[nt] = (bl + 4) * 512 + (c1 << 4) + nw * 4;
    }

    float acc[4][4][4];
#pragma unroll
    for (int a = 0; a < 4; a++)
#pragma unroll
        for (int b = 0; b < 4; b++)
#pragma unroll
            for (int c = 0; c < 4; c++) acc[a][b][c] = 0.f;

    float4 av[4], bv[4];
    auto loadc = [&](int c) {
        if (PASS == 1) {
#pragma unroll
            for (int i = 0; i < 4; i++) av[i] = ap4[i][c * 8];
        } else {
#pragma unroll
            for (int i = 0; i < 4; i++) {
                uint2 hv = ah2[i][c * 8];
                __half2 p0 = *(__half2*)&hv.x;
                __half2 p1 = *(__half2*)&hv.y;
                float2 f0 = __half22float2(p0);
                float2 f1 = __half22float2(p1);
                av[i] = make_float4(f0.x, f0.y, f1.x, f1.y);
            }
        }
#pragma unroll
        for (int i = 0; i < 4; i++) bv[i] = bp4[c * 8192 + i * 2048];
    };
    auto stores = [&](int buf) {
        uint32_t base = sb + buf * STAGE_BYTES;
#pragma unroll
        for (int i = 0; i < 4; i++)
            sts128(base + astA[i], f2tf(av[i].x), f2tf(av[i].y), f2tf(av[i].z), f2tf(av[i].w));
#pragma unroll
        for (int i = 0; i < 4; i++)
            sts128(base + SM_B + bst[i], f2tf(bv[i].x), f2tf(bv[i].y), f2tf(bv[i].z), f2tf(bv[i].w));
    };
    auto compute = [&](int buf) {
        uint32_t ab = sb + buf * STAGE_BYTES;
        uint32_t bb = ab + SM_B;
#pragma unroll
        for (int ks = 0; ks < 4; ks++) {
            uint32_t Af[4][4], B0[4], B1[4];
#pragma unroll
            for (int mt = 0; mt < 4; mt++) {
                uint32_t chunk = (uint32_t)(ks * 2) + kc;
                uint32_t addr  = ab + rowb[mt] + ((chunk ^ r7[mt]) << 4);
                ldsm4(Af[mt], addr);
            }
#pragma unroll
            for (int nt = 0; nt < 4; nt++) {
                B0[nt] = lds32(bb + ks * 4096 + bB0[nt]);
                B1[nt] = lds32(bb + ks * 4096 + bB1[nt]);
            }
#pragma unroll
            for (int mt = 0; mt < 4; mt++)
#pragma unroll
                for (int nt = 0; nt < 4; nt++)
                    mma_tf32(acc[mt][nt], Af[mt], B0[nt], B1[nt]);
        }
    };

    // Schedule: compute(c); loadc(c+1); stores(c+1); sync.  (R15, proven at occ 2)
    loadc(0);
    stores(0);
    __syncthreads();
#pragma unroll 1
    for (int c = 0; c < NCH; c++) {
        compute(c & 1);
        if (c + 1 < NCH) {
            loadc(c + 1);
            stores((c + 1) & 1);
        }
        __syncthreads();
    }

    // ---- epilogue (fp16 stores) ----
    float bs[4][2];
#pragma unroll
    for (int nt = 0; nt < 4; nt++) {
        int col = n0 + wn + nt * 8 + (lane & 3) * 2;
        bs[nt][0] = Bias[(size_t)e * EMB + col];
        bs[nt][1] = Bias[(size_t)e * EMB + col + 1];
    }
#pragma unroll
    for (int mt = 0; mt < 4; mt++)
#pragma unroll
        for (int h = 0; h < 2; h++) {
            int m = mbase + wm + mt * 16 + (lane >> 2) + h * 8;
            if (m >= cnt) continue;
            __half* dst = (PASS == 1 ? g_h : g_y) + (size_t)(off + m) * EMB + n0 + wn;
#pragma unroll
            for (int nt = 0; nt < 4; nt++) {
                float v0 = acc[mt][nt][h * 2 + 0] + bs[nt][0];
                float v1 = acc[mt][nt][h * 2 + 1] + bs[nt][1];
                if (PASS == 1) { v0 = fmaxf(v0, 0.f); v1 = fmaxf(v1, 0.f); }
                int col = nt * 8 + (lane & 3) * 2;
                *(__half2*)(dst + col) = __floats2half2_rn(v0, v1);
            }
        }
}

// out[t] = w0 * y[slot(t,0)] + w1 * y[slot(t,1)]   (fp16 y, fp32 out)
__global__ __launch_bounds__(256) void combine_kernel(float* __restrict__ out) {
    int idx = blockIdx.x * 256 + threadIdx.x;     // T_TOK * EMB/4 threads
    int t   = idx >> 8;                            // EMB/4 = 256
    int d4  = idx & 255;
    int s0 = g_tok_slot[2 * t], s1 = g_tok_slot[2 * t + 1];
    float w0 = g_tok_w[2 * t], w1 = g_tok_w[2 * t + 1];
    uint2 ya = *((const uint2*)(g_y + (size_t)s0 * EMB) + d4);
    uint2 yb = *((const uint2*)(g_y + (size_t)s1 * EMB) + d4);
    float2 a0 = __half22float2(*(__half2*)&ya.x);
    float2 a1 = __half22float2(*(__half2*)&ya.y);
    float2 b0 = __half22float2(*(__half2*)&yb.x);
    float2 b1 = __half22float2(*(__half2*)&yb.y);
    float4 o;
    o.x = w0 * a0.x + w1 * b0.x;
    o.y = w0 * a0.y + w1 * b0.y;
    o.z = w0 * a1.x + w1 * b1.x;
    o.w = w0 * a1.y + w1 * b1.y;
    *((float4*)(out + (size_t)t * EMB) + d4) = o;
}

extern "C" void kernel_launch(void* const* d_in, const int* in_sizes, int n_in,
                              void* d_out, int out_size) {
    const float* x  = (const float*)d_in[0];
    const float* gw = (const float*)d_in[1];
    const float* gb = (const float*)d_in[2];
    const float* W1 = (const float*)d_in[3];
    const float* b1 = (const float*)d_in[4];
    const float* W2 = (const float*)d_in[5];
    const float* b2 = (const float*)d_in[6];
    float* out = (float*)d_out;

    cudaFuncSetAttribute(moe_mma<1>, cudaFuncAttributeMaxDynamicSharedMemorySize, SMEM_BYTES);
    cudaFuncSetAttribute(moe_mma<2>, cudaFuncAttributeMaxDynamicSharedMemorySize, SMEM_BYTES);

    // no memset: combine_kernel fully overwrites d_out.
    reset_kernel<<<1, 32>>>();
    gate_kernel<<<T_TOK / 8, 256>>>(x, gw, gb);
    scan_kernel<<<1, 1>>>();
    scatter_kernel<<<NSLOT / 256, 256>>>();

    dim3 grid(EMB / BN, NSLOT / BM, NEXP);
    moe_mma<1><<<grid, 256, SMEM_BYTES>>>(x, W1, b1);
    moe_mma<2><<<grid, 256, SMEM_BYTES>>>(nullptr, W2, b2);
    combine_kernel<<<T_TOK * (EMB / 4) / 256, 256>>>(out);
}